// round 12
// baseline (speedup 1.0000x reference)
#include <cuda_runtime.h>
#include <cuda_bf16.h>
#include <math.h>
#include <stdint.h>

// ===========================================================================
// Problem dims
// ===========================================================================
constexpr int B_ = 8;
constexpr int S_ = 2048;
constexpr int H_ = 1024;
constexpr int NH_ = 16;
constexpr int DH_ = 64;
constexpr int M_ = B_ * S_;   // 16384
constexpr int N_ = H_;        // 1024
constexpr int K_ = H_;        // 1024
constexpr int SCTX_SPLIT = 4;  // S-dimension split for sctx

// ===========================================================================
// Scratch (device globals: allocation-guard safe)
// ===========================================================================
__device__ __nv_bfloat16 g_xh[(size_t)M_ * K_];
__device__ __nv_bfloat16 g_xl[(size_t)M_ * K_];
__device__ __nv_bfloat16 g_wht[3][(size_t)N_ * K_];   // W^T [n][k], hi part
__device__ __nv_bfloat16 g_wlt[3][(size_t)N_ * K_];   // W^T [n][k], lo part
__device__ float g_q[(size_t)M_ * N_];
__device__ float g_k[(size_t)M_ * N_];
__device__ float g_v[(size_t)M_ * N_];
__device__ float g_l_part[SCTX_SPLIT][B_ * NH_][DH_];
__device__ float g_sctx_part[SCTX_SPLIT][B_ * NH_][DH_ * DH_];
__device__ float g_sctx[B_ * NH_ * DH_ * DH_];

// ===========================================================================
// PTX helpers (sm_103 BASE target — no 'a'-only features!)
// ===========================================================================
__device__ __forceinline__ uint32_t smem_to_u32(const void* p) {
    uint32_t a;
    asm("{ .reg .u64 t; cvta.to.shared.u64 t, %1; cvt.u32.u64 %0, t; }"
        : "=r"(a) : "l"(p));
    return a;
}

#define CP_ASYNC16(dst_u32, src_ptr) \
    asm volatile("cp.async.cg.shared.global [%0], [%1], 16;" \
                 :: "r"(dst_u32), "l"(src_ptr))
#define CP_COMMIT() asm volatile("cp.async.commit_group;" ::: "memory")
#define CP_WAIT1()  asm volatile("cp.async.wait_group 1;" ::: "memory")
#define CP_WAIT0()  asm volatile("cp.async.wait_group 0;" ::: "memory")

#define LDSM_X4(r0, r1, r2, r3, addr) \
    asm volatile("ldmatrix.sync.aligned.m8n8.x4.shared.b16 {%0,%1,%2,%3}, [%4];" \
                 : "=r"(r0), "=r"(r1), "=r"(r2), "=r"(r3) : "r"(addr))

#define MMA16816(d, a, b0, b1) \
    asm volatile("mma.sync.aligned.m16n8k16.row.col.f32.bf16.bf16.f32 " \
                 "{%0,%1,%2,%3}, {%4,%5,%6,%7}, {%8,%9}, {%0,%1,%2,%3};" \
                 : "+f"((d)[0]), "+f"((d)[1]), "+f"((d)[2]), "+f"((d)[3]) \
                 : "r"((a)[0]), "r"((a)[1]), "r"((a)[2]), "r"((a)[3]), \
                   "r"(b0), "r"(b1))

// Blackwell packed fp32 pair FMA (base sm_100-family PTX; NOT 'a'-gated)
#define FMA_F32X2(acc, a, b) \
    asm("fma.rn.f32x2 %0, %1, %2, %0;" : "+l"(acc) : "l"(a), "l"(b))
#define PACK_F32X2(out, lo, hi) \
    asm("mov.b64 %0, {%1, %2};" : "=l"(out) \
        : "r"(__float_as_uint(lo)), "r"(__float_as_uint(hi)))
#define DUP_F32X2(out, f) \
    asm("mov.b64 %0, {%1, %1};" : "=l"(out) : "r"(__float_as_uint(f)))
#define UNPACK_F32X2(lo, hi, in) do { \
    uint32_t _l, _h; \
    asm("mov.b64 {%0, %1}, %2;" : "=r"(_l), "=r"(_h) : "l"(in)); \
    lo = __uint_as_float(_l); hi = __uint_as_float(_h); \
} while (0)

// ===========================================================================
// Kernel A1: split X (fp32 -> bf16 hi + bf16 residual)
// ===========================================================================
__global__ void split_x_kernel(const float* __restrict__ X)
{
    size_t i = (size_t)blockIdx.x * 256 + threadIdx.x;      // float4 index
    float4 v = ((const float4*)X)[i];
    __nv_bfloat16 h0 = __float2bfloat16(v.x);
    __nv_bfloat16 h1 = __float2bfloat16(v.y);
    __nv_bfloat16 h2 = __float2bfloat16(v.z);
    __nv_bfloat16 h3 = __float2bfloat16(v.w);
    __nv_bfloat16 l0 = __float2bfloat16(v.x - __bfloat162float(h0));
    __nv_bfloat16 l1 = __float2bfloat16(v.y - __bfloat162float(h1));
    __nv_bfloat16 l2 = __float2bfloat16(v.z - __bfloat162float(h2));
    __nv_bfloat16 l3 = __float2bfloat16(v.w - __bfloat162float(h3));
    __nv_bfloat162* ph = (__nv_bfloat162*)g_xh;
    __nv_bfloat162* pl = (__nv_bfloat162*)g_xl;
    ph[i * 2 + 0] = __halves2bfloat162(h0, h1);
    ph[i * 2 + 1] = __halves2bfloat162(h2, h3);
    pl[i * 2 + 0] = __halves2bfloat162(l0, l1);
    pl[i * 2 + 1] = __halves2bfloat162(l2, l3);
}

// ===========================================================================
// Kernel A2: split + transpose W[K,N] -> Wt[N,K] (hi/lo bf16)
// ===========================================================================
__global__ void split_w_kernel(const float* __restrict__ Wq,
                               const float* __restrict__ Wk,
                               const float* __restrict__ Wv)
{
    int which = blockIdx.z;
    const float* W = (which == 0) ? Wq : (which == 1) ? Wk : Wv;
    __shared__ float t[32][33];
    int n0 = blockIdx.x * 32, k0 = blockIdx.y * 32;
    int tx = threadIdx.x, ty = threadIdx.y;
    #pragma unroll
    for (int r = 0; r < 4; r++)
        t[ty + r * 8][tx] = W[(size_t)(k0 + ty + r * 8) * N_ + n0 + tx];
    __syncthreads();
    #pragma unroll
    for (int r = 0; r < 4; r++) {
        int n = n0 + ty + r * 8, k = k0 + tx;
        float v = t[tx][ty + r * 8];
        __nv_bfloat16 h = __float2bfloat16(v);
        g_wht[which][(size_t)n * K_ + k] = h;
        g_wlt[which][(size_t)n * K_ + k] = __float2bfloat16(v - __bfloat162float(h));
    }
}

// ===========================================================================
// Kernel B: QKV GEMM via mma.sync (HMMA bf16), bf16x3 split, register reuse.
// CTA tile 128x256, BK=64, 16 warps (32x64 warp tiles: 4 warp_m x 4 warp_n),
// 2-stage cp.async pipeline. Stage = A(h,l) 32KB + B(h,l) 64KB = 96KB.
// Inner loop keeps peak live regs ~108 (< 128 cap at 512 threads).
// grid (N/256=4, M/128=128, 3) = 1536 CTAs, 512 threads, 192KB smem.
// [FROZEN — audited R3/R4/R6/R7]
// ===========================================================================
constexpr int TILE_A_BYTES = 16384;            // 128x64 bf16
constexpr int TILE_B_BYTES = 32768;            // 256x64 bf16
constexpr int STAGE_BYTES  = 2 * TILE_A_BYTES + 2 * TILE_B_BYTES;  // 96KB
constexpr int GEMM_SMEM    = 2 * STAGE_BYTES;  // 192KB

__global__ __launch_bounds__(512, 1) void qkv_gemm_kernel(
    const float* __restrict__ bq, const float* __restrict__ bk,
    const float* __restrict__ bv)
{
    extern __shared__ char dsm[];
    const uint32_t smem_u32 = smem_to_u32(dsm);

    const int tid  = threadIdx.x;
    const int wid  = tid >> 5;
    const int lane = tid & 31;
    const int warp_m = wid & 3;        // 4 -> m dimension (32 rows each)
    const int warp_n = wid >> 2;       // 4 -> n dimension (64 cols each)
    const int n0 = blockIdx.x * 256;
    const int m0 = blockIdx.y * 128;
    const int which = blockIdx.z;

    const __nv_bfloat16* Bh = g_wht[which];
    const __nv_bfloat16* Bl = g_wlt[which];

    auto issue_load = [&](int kc, int stage) {
        const size_t koff = (size_t)kc * 64;
        const uint32_t sAh = smem_u32 + stage * STAGE_BYTES;
        const uint32_t sAl = sAh + TILE_A_BYTES;
        const uint32_t sBh = sAh + 2 * TILE_A_BYTES;
        const uint32_t sBl = sBh + TILE_B_BYTES;
        #pragma unroll
        for (int j = 0; j < 2; j++) {
            int ch  = tid + j * 512;         // 0..1023
            int row = ch >> 3;               // 0..127
            int c   = ch & 7;
            uint32_t so = (uint32_t)(row * 128 + ((c ^ (row & 7)) * 16));
            const size_t aoff = (size_t)(m0 + row) * K_ + koff + c * 8;
            CP_ASYNC16(sAh + so, g_xh + aoff);
            CP_ASYNC16(sAl + so, g_xl + aoff);
        }
        #pragma unroll
        for (int j = 0; j < 4; j++) {
            int ch  = tid + j * 512;         // 0..2047
            int row = ch >> 3;               // 0..255
            int c   = ch & 7;
            uint32_t so = (uint32_t)(row * 128 + ((c ^ (row & 7)) * 16));
            const size_t boff = (size_t)(n0 + row) * K_ + koff + c * 8;
            CP_ASYNC16(sBh + so, Bh + boff);
            CP_ASYNC16(sBl + so, Bl + boff);
        }
        CP_COMMIT();
    };

    const int aRow = warp_m * 32 + (lane & 15);
    const uint32_t aOff0 = (uint32_t)(aRow * 128);
    const uint32_t aOff1 = (uint32_t)((aRow + 16) * 128);
    const int aXor = aRow & 7;
    const int aCsel = lane >> 4;
    const int bRow = warp_n * 64 + ((lane >> 4) << 3) + (lane & 7);   // 0..255
    const int bXor = bRow & 7;
    const int bCsel = (lane >> 3) & 1;
    uint32_t bOff[4];
    #pragma unroll
    for (int g = 0; g < 4; g++) bOff[g] = (uint32_t)((bRow + g * 16) * 128);

    float acc[2][8][4];
    #pragma unroll
    for (int mt = 0; mt < 2; mt++)
        #pragma unroll
        for (int nt = 0; nt < 8; nt++)
            #pragma unroll
            for (int r = 0; r < 4; r++) acc[mt][nt][r] = 0.f;

    issue_load(0, 0);
    issue_load(1, 1);

    for (int kc = 0; kc < 16; kc++) {
        if (kc < 15) CP_WAIT1(); else CP_WAIT0();
        __syncthreads();

        const uint32_t sAh = smem_u32 + (kc & 1) * STAGE_BYTES;
        const uint32_t sAl = sAh + TILE_A_BYTES;
        const uint32_t sBh = sAh + 2 * TILE_A_BYTES;
        const uint32_t sBl = sBh + TILE_B_BYTES;

        #pragma unroll
        for (int ks = 0; ks < 4; ks++) {
            const int ca = ((ks * 2 + aCsel) ^ aXor) * 16;
            const int cb = ((ks * 2 + bCsel) ^ bXor) * 16;

            uint32_t afh[2][4], afl[2][4];
            LDSM_X4(afh[0][0], afh[0][1], afh[0][2], afh[0][3], sAh + aOff0 + ca);
            LDSM_X4(afh[1][0], afh[1][1], afh[1][2], afh[1][3], sAh + aOff1 + ca);
            LDSM_X4(afl[0][0], afl[0][1], afl[0][2], afl[0][3], sAl + aOff0 + ca);
            LDSM_X4(afl[1][0], afl[1][1], afl[1][2], afl[1][3], sAl + aOff1 + ca);

            #pragma unroll
            for (int g = 0; g < 4; g++) {
                uint32_t bfh[4], bfl[4];
                LDSM_X4(bfh[0], bfh[1], bfh[2], bfh[3], sBh + bOff[g] + cb);
                LDSM_X4(bfl[0], bfl[1], bfl[2], bfl[3], sBl + bOff[g] + cb);

                #pragma unroll
                for (int mt = 0; mt < 2; mt++) {
                    MMA16816(acc[mt][g * 2 + 0], afh[mt], bfh[0], bfh[1]);
                    MMA16816(acc[mt][g * 2 + 1], afh[mt], bfh[2], bfh[3]);
                    MMA16816(acc[mt][g * 2 + 0], afh[mt], bfl[0], bfl[1]);
                    MMA16816(acc[mt][g * 2 + 1], afh[mt], bfl[2], bfl[3]);
                    MMA16816(acc[mt][g * 2 + 0], afl[mt], bfh[0], bfh[1]);
                    MMA16816(acc[mt][g * 2 + 1], afl[mt], bfh[2], bfh[3]);
                }
            }
        }
        __syncthreads();
        if (kc + 2 < 16) issue_load(kc + 2, kc & 1);
    }

    float* C = (which == 0) ? g_q : (which == 1) ? g_k : g_v;
    const float* bias = (which == 0) ? bq : (which == 1) ? bk : bv;

    #pragma unroll
    for (int mt = 0; mt < 2; mt++) {
        const int r0 = m0 + warp_m * 32 + mt * 16 + (lane >> 2);
        #pragma unroll
        for (int nt = 0; nt < 8; nt++) {
            const int col = n0 + warp_n * 64 + nt * 8 + (lane & 3) * 2;
            const float b0v = __ldg(&bias[col]);
            const float b1v = __ldg(&bias[col + 1]);
            float2 v0 = make_float2(acc[mt][nt][0] + b0v, acc[mt][nt][1] + b1v);
            float2 v1 = make_float2(acc[mt][nt][2] + b0v, acc[mt][nt][3] + b1v);
            *(float2*)&C[(size_t)r0 * N_ + col] = v0;
            *(float2*)&C[(size_t)(r0 + 8) * N_ + col] = v1;
        }
    }
}

// ===========================================================================
// Kernel 3: partial s_ctx over an S-slice + per-column exp-sum.
// Inner product on packed fma.rn.f32x2 (2 FMA per issue slot).
// grid (B*NH, SCTX_SPLIT), 256 threads. Each CTA: 512 s-steps.
// ===========================================================================
__global__ __launch_bounds__(256) void sctx_kernel(const float* __restrict__ mask)
{
    const int bh = blockIdx.x;
    const int part = blockIdx.y;
    const int b = bh >> 4;
    const int h = bh & 15;
    const int tid = threadIdx.x;

    __shared__ float qs[32][64];
    __shared__ float vs[32][64];
    __shared__ float lred[4][64];

    const int i4 = (tid / 16) * 4;
    const int j4 = (tid % 16) * 4;
    const int myc = tid & 63;          // fixed column this thread loads

    uint64_t acc2[4][2];               // packed (col j4+2jp, j4+2jp+1) per row i
    #pragma unroll
    for (int i = 0; i < 4; i++) { acc2[i][0] = 0ull; acc2[i][1] = 0ull; }
    float lsum = 0.f;

    const float* qb = g_q + (size_t)b * S_ * H_ + h * 64;
    const float* vb = g_v + (size_t)b * S_ * H_ + h * 64;
    const float* mb = mask + b * S_;

    const int sBeg = part * (S_ / SCTX_SPLIT);
    const int sEnd = sBeg + (S_ / SCTX_SPLIT);

    for (int s0 = sBeg; s0 < sEnd; s0 += 32) {
        #pragma unroll
        for (int e = 0; e < 8; e++) {
            int idx = tid + e * 256;
            int r = idx >> 6, c = idx & 63;      // c == myc for all e
            float ev = __expf(qb[(size_t)(s0 + r) * H_ + c] + mb[s0 + r]);
            qs[r][c] = ev;
            lsum += ev;
            vs[r][c] = vb[(size_t)(s0 + r) * H_ + c];
        }
        __syncthreads();

        #pragma unroll
        for (int s = 0; s < 32; s++) {
            float ra[4];
            *(float4*)ra = *(const float4*)&qs[s][i4];
            uint64_t b0 = *(const uint64_t*)&vs[s][j4];      // (v[j4],v[j4+1])
            uint64_t b1 = *(const uint64_t*)&vs[s][j4 + 2];
            #pragma unroll
            for (int i = 0; i < 4; i++) {
                uint64_t ad;
                DUP_F32X2(ad, ra[i]);
                FMA_F32X2(acc2[i][0], ad, b0);
                FMA_F32X2(acc2[i][1], ad, b1);
            }
        }
        __syncthreads();
    }

    // reduce the 4 row-groups' l partials per column
    lred[tid >> 6][myc] = lsum;
    __syncthreads();
    if (tid < 64)
        g_l_part[part][bh][tid] =
            lred[0][tid] + lred[1][tid] + lred[2][tid] + lred[3][tid];

    float* outp = g_sctx_part[part][bh];
    #pragma unroll
    for (int i = 0; i < 4; i++) {
        float lo0, hi0, lo1, hi1;
        UNPACK_F32X2(lo0, hi0, acc2[i][0]);
        UNPACK_F32X2(lo1, hi1, acc2[i][1]);
        float4 o = make_float4(lo0, hi0, lo1, hi1);
        *(float4*)&outp[(i4 + i) * 64 + j4] = o;
    }
}

// ===========================================================================
// Kernel 3b: reduce Y and l partials + apply 1/l scaling.
// ===========================================================================
__global__ __launch_bounds__(256) void sctx_reduce_kernel()
{
    const int bh = blockIdx.x;
    const int tid = threadIdx.x;

    __shared__ float ilsh[64];
    if (tid < 64) {
        float l = g_l_part[0][bh][tid] + g_l_part[1][bh][tid]
                + g_l_part[2][bh][tid] + g_l_part[3][bh][tid];
        ilsh[tid] = 1.f / l;
    }
    __syncthreads();

    #pragma unroll
    for (int e = 0; e < 4; e++) {
        int i = (tid + e * 256) * 4;       // float4 element base
        float4 s0 = *(const float4*)&g_sctx_part[0][bh][i];
        float4 s1 = *(const float4*)&g_sctx_part[1][bh][i];
        float4 s2 = *(const float4*)&g_sctx_part[2][bh][i];
        float4 s3 = *(const float4*)&g_sctx_part[3][bh][i];
        float il = ilsh[i >> 6];           // row d = i/64
        float4 o;
        o.x = (s0.x + s1.x + s2.x + s3.x) * il;
        o.y = (s0.y + s1.y + s2.y + s3.y) * il;
        o.z = (s0.z + s1.z + s2.z + s3.z) * il;
        o.w = (s0.w + s1.w + s2.w + s3.w) * il;
        *(float4*)&g_sctx[(size_t)bh * 4096 + i] = o;
    }
}

// ===========================================================================
// Kernel 4: out = softmax64(K rows) @ s_ctx.
// v4: d-pairwise packed fma.rn.f32x2. cs pairs are contiguous -> LDS.64
// directly as packed operand; sv pairs packed once per 16-d chunk
// (amortized over 8 rows). Horizontal add at the end.
// grid (S/64=32, B*NH=128), 256 threads.
// ===========================================================================
constexpr int OUT_ROWS_PER_WARP = 8;

__global__ __launch_bounds__(256) void out_kernel(float* __restrict__ out)
{
    const int bh = blockIdx.y;
    const int b = bh >> 4;
    const int h = bh & 15;
    const int warp = threadIdx.x >> 5;
    const int lane = threadIdx.x & 31;

    __shared__ float ss[4096];
    __shared__ float cs[8][OUT_ROWS_PER_WARP][64];   // softmax weights per warp/row
    const float* sc = g_sctx + (size_t)bh * 4096;
    for (int i = threadIdx.x; i < 4096; i += 256) ss[i] = sc[i];
    __syncthreads();

    const int sBase = blockIdx.x * (8 * OUT_ROWS_PER_WARP) + warp * OUT_ROWS_PER_WARP;
    const float* kb0 = g_k + ((size_t)b * S_ + sBase) * H_ + h * 64;

    // batched K loads for all 8 rows (MLP=16)
    float kv0[OUT_ROWS_PER_WARP], kv1[OUT_ROWS_PER_WARP];
    #pragma unroll
    for (int i = 0; i < OUT_ROWS_PER_WARP; i++) {
        kv0[i] = kb0[(size_t)i * H_ + lane];
        kv1[i] = kb0[(size_t)i * H_ + lane + 32];
    }

    // softmax weights (no max subtraction needed: |k| small) -> stage to smem
    #pragma unroll
    for (int i = 0; i < OUT_ROWS_PER_WARP; i++) {
        float e0 = __expf(kv0[i]), e1 = __expf(kv1[i]);
        float sum = e0 + e1;
        #pragma unroll
        for (int off = 16; off; off >>= 1)
            sum += __shfl_xor_sync(0xffffffffu, sum, off);
        float inv = 1.f / sum;
        cs[warp][i][lane]      = e0 * inv;
        cs[warp][i][lane + 32] = e1 * inv;
    }
    __syncwarp();

    // main product on packed f32x2, pairwise along d.
    uint64_t accp0[OUT_ROWS_PER_WARP], accp1[OUT_ROWS_PER_WARP];
    #pragma unroll
    for (int i = 0; i < OUT_ROWS_PER_WARP; i++) { accp0[i] = 0ull; accp1[i] = 0ull; }

    #pragma unroll
    for (int dc = 0; dc < 4; dc++) {
        float sv0[16], sv1[16];
        #pragma unroll
        for (int d = 0; d < 16; d++) {
            sv0[d] = ss[(dc * 16 + d) * 64 + lane];
            sv1[d] = ss[(dc * 16 + d) * 64 + lane + 32];
        }
        uint64_t sp0[8], sp1[8];
        #pragma unroll
        for (int p = 0; p < 8; p++) {
            PACK_F32X2(sp0[p], sv0[2 * p], sv0[2 * p + 1]);
            PACK_F32X2(sp1[p], sv1[2 * p], sv1[2 * p + 1]);
        }
        #pragma unroll
        for (int i = 0; i < OUT_ROWS_PER_WARP; i++) {
            #pragma unroll
            for (int p = 0; p < 8; p++) {
                uint64_t cpair = *(const uint64_t*)&cs[warp][i][dc * 16 + 2 * p];
                FMA_F32X2(accp0[i], cpair, sp0[p]);
                FMA_F32X2(accp1[i], cpair, sp1[p]);
            }
        }
    }

    #pragma unroll
    for (int i = 0; i < OUT_ROWS_PER_WARP; i++) {
        float l0, h0, l1, h1;
        UNPACK_F32X2(l0, h0, accp0[i]);
        UNPACK_F32X2(l1, h1, accp1[i]);
        float* ob = out + ((size_t)b * S_ + sBase + i) * H_ + h * 64;
        ob[lane]      = l0 + h0;
        ob[lane + 32] = l1 + h1;
    }
}

// ===========================================================================
extern "C" void kernel_launch(void* const* d_in, const int* in_sizes, int n_in,
                              void* d_out, int out_size)
{
    const float* X    = (const float*)d_in[0];
    const float* mask = (const float*)d_in[1];
    const float* Wq   = (const float*)d_in[2];
    const float* bq   = (const float*)d_in[3];
    const float* Wk   = (const float*)d_in[4];
    const float* bk   = (const float*)d_in[5];
    const float* Wv   = (const float*)d_in[6];
    const float* bv   = (const float*)d_in[7];
    float* out = (float*)d_out;

    cudaFuncSetAttribute(qkv_gemm_kernel,
                         cudaFuncAttributeMaxDynamicSharedMemorySize, GEMM_SMEM);

    // prep: bf16 splits (+ W transpose)
    split_x_kernel<<<(int)((size_t)M_ * K_ / 4 / 256), 256>>>(X);
    split_w_kernel<<<dim3(N_ / 32, K_ / 32, 3), dim3(32, 8)>>>(Wq, Wk, Wv);

    // HMMA QKV GEMMs (128x256 tiles, spill-free inner loop)
    qkv_gemm_kernel<<<dim3(N_ / 256, M_ / 128, 3), 512, GEMM_SMEM>>>(bq, bk, bv);

    // attention tail (stats fused into sctx; f32x2 packed FMA inner loops)
    sctx_kernel<<<dim3(B_ * NH_, SCTX_SPLIT), 256>>>(mask);
    sctx_reduce_kernel<<<B_ * NH_, 256>>>();
    out_kernel<<<dim3(S_ / 64, B_ * NH_), 256>>>(out);
}

// round 16
// speedup vs baseline: 1.4674x; 1.4674x over previous
#include <cuda_runtime.h>
#include <cuda_fp16.h>
#include <math.h>
#include <stdint.h>

// ===========================================================================
// Problem dims
// ===========================================================================
constexpr int B_ = 8;
constexpr int S_ = 2048;
constexpr int H_ = 1024;
constexpr int NH_ = 16;
constexpr int DH_ = 64;
constexpr int M_ = B_ * S_;   // 16384
constexpr int N_ = H_;        // 1024
constexpr int K_ = H_;        // 1024
constexpr int SCTX_SPLIT = 8;  // S-dimension split for sctx

// ===========================================================================
// Scratch (device globals: allocation-guard safe)
// ===========================================================================
__device__ __half g_xh[(size_t)M_ * K_];       // X hi (fp16)
__device__ __half g_xl[(size_t)M_ * K_];       // X residual (fp16)
__device__ __half g_wt[3][(size_t)N_ * K_];    // W^T [n][k] single fp16
__device__ float g_q[(size_t)M_ * N_];
__device__ float g_k[(size_t)M_ * N_];
__device__ float g_v[(size_t)M_ * N_];
__device__ float g_l_part[SCTX_SPLIT][B_ * NH_][DH_];
__device__ float g_sctx_part[SCTX_SPLIT][B_ * NH_][DH_ * DH_];
__device__ float g_sctx[B_ * NH_ * DH_ * DH_];

// ===========================================================================
// PTX helpers (sm_103 BASE target — no 'a'-only features!)
// ===========================================================================
__device__ __forceinline__ uint32_t smem_to_u32(const void* p) {
    uint32_t a;
    asm("{ .reg .u64 t; cvta.to.shared.u64 t, %1; cvt.u32.u64 %0, t; }"
        : "=r"(a) : "l"(p));
    return a;
}

#define CP_ASYNC16(dst_u32, src_ptr) \
    asm volatile("cp.async.cg.shared.global [%0], [%1], 16;" \
                 :: "r"(dst_u32), "l"(src_ptr))
#define CP_COMMIT() asm volatile("cp.async.commit_group;" ::: "memory")
#define CP_WAIT1()  asm volatile("cp.async.wait_group 1;" ::: "memory")
#define CP_WAIT0()  asm volatile("cp.async.wait_group 0;" ::: "memory")

#define LDSM_X4(r0, r1, r2, r3, addr) \
    asm volatile("ldmatrix.sync.aligned.m8n8.x4.shared.b16 {%0,%1,%2,%3}, [%4];" \
                 : "=r"(r0), "=r"(r1), "=r"(r2), "=r"(r3) : "r"(addr))

// fp16 inputs, fp32 accumulate
#define MMAF16(d, a, b0, b1) \
    asm volatile("mma.sync.aligned.m16n8k16.row.col.f32.f16.f16.f32 " \
                 "{%0,%1,%2,%3}, {%4,%5,%6,%7}, {%8,%9}, {%0,%1,%2,%3};" \
                 : "+f"((d)[0]), "+f"((d)[1]), "+f"((d)[2]), "+f"((d)[3]) \
                 : "r"((a)[0]), "r"((a)[1]), "r"((a)[2]), "r"((a)[3]), \
                   "r"(b0), "r"(b1))

// Blackwell packed fp32 pair FMA (base sm_100-family PTX; NOT 'a'-gated)
#define FMA_F32X2(acc, a, b) \
    asm("fma.rn.f32x2 %0, %1, %2, %0;" : "+l"(acc) : "l"(a), "l"(b))
#define PACK_F32X2(out, lo, hi) \
    asm("mov.b64 %0, {%1, %2};" : "=l"(out) \
        : "r"(__float_as_uint(lo)), "r"(__float_as_uint(hi)))
#define DUP_F32X2(out, f) \
    asm("mov.b64 %0, {%1, %1};" : "=l"(out) : "r"(__float_as_uint(f)))
#define UNPACK_F32X2(lo, hi, in) do { \
    uint32_t _l, _h; \
    asm("mov.b64 {%0, %1}, %2;" : "=r"(_l), "=r"(_h) : "l"(in)); \
    lo = __uint_as_float(_l); hi = __uint_as_float(_h); \
} while (0)

// ===========================================================================
// Kernel A1: split X (fp32 -> fp16 hi + fp16 residual)
// ===========================================================================
__global__ void split_x_kernel(const float* __restrict__ X)
{
    size_t i = (size_t)blockIdx.x * 256 + threadIdx.x;      // float4 index
    float4 v = ((const float4*)X)[i];
    __half h0 = __float2half(v.x);
    __half h1 = __float2half(v.y);
    __half h2 = __float2half(v.z);
    __half h3 = __float2half(v.w);
    __half l0 = __float2half(v.x - __half2float(h0));
    __half l1 = __float2half(v.y - __half2float(h1));
    __half l2 = __float2half(v.z - __half2float(h2));
    __half l3 = __float2half(v.w - __half2float(h3));
    __half2* ph = (__half2*)g_xh;
    __half2* pl = (__half2*)g_xl;
    ph[i * 2 + 0] = __halves2half2(h0, h1);
    ph[i * 2 + 1] = __halves2half2(h2, h3);
    pl[i * 2 + 0] = __halves2half2(l0, l1);
    pl[i * 2 + 1] = __halves2half2(l2, l3);
}

// ===========================================================================
// Kernel A2: transpose W[K,N] -> Wt[N,K] single fp16
// ===========================================================================
__global__ void split_w_kernel(const float* __restrict__ Wq,
                               const float* __restrict__ Wk,
                               const float* __restrict__ Wv)
{
    int which = blockIdx.z;
    const float* W = (which == 0) ? Wq : (which == 1) ? Wk : Wv;
    __shared__ float t[32][33];
    int n0 = blockIdx.x * 32, k0 = blockIdx.y * 32;
    int tx = threadIdx.x, ty = threadIdx.y;
    #pragma unroll
    for (int r = 0; r < 4; r++)
        t[ty + r * 8][tx] = W[(size_t)(k0 + ty + r * 8) * N_ + n0 + tx];
    __syncthreads();
    #pragma unroll
    for (int r = 0; r < 4; r++) {
        int n = n0 + ty + r * 8, k = k0 + tx;
        g_wt[which][(size_t)n * K_ + k] = __float2half(t[tx][ty + r * 8]);
    }
}

// ===========================================================================
// Kernel B: QKV GEMM via mma.sync (HMMA fp16), fp16x2 split (A hi/lo, B
// single fp16 — error ~2^-11/sqrt(3) ≈ 3e-4 from B rounding only).
// CTA tile 128x256, BK=64, 16 warps (32x64 warp tiles), 2-stage cp.async.
// Stage = Ah 16KB + Al 16KB + B 32KB = 64KB; 2048 MMAs/CTA (was 3072).
// grid (N/256=4, M/128=128, 3) = 1536 CTAs, 512 threads, 128KB smem.
// ===========================================================================
constexpr int TILE_A_BYTES = 16384;            // 128x64 fp16
constexpr int TILE_B_BYTES = 32768;            // 256x64 fp16
constexpr int STAGE_BYTES  = 2 * TILE_A_BYTES + TILE_B_BYTES;  // 64KB
constexpr int GEMM_SMEM    = 2 * STAGE_BYTES;  // 128KB

__global__ __launch_bounds__(512, 1) void qkv_gemm_kernel(
    const float* __restrict__ bq, const float* __restrict__ bk,
    const float* __restrict__ bv)
{
    extern __shared__ char dsm[];
    const uint32_t smem_u32 = smem_to_u32(dsm);

    const int tid  = threadIdx.x;
    const int wid  = tid >> 5;
    const int lane = tid & 31;
    const int warp_m = wid & 3;        // 4 -> m dimension (32 rows each)
    const int warp_n = wid >> 2;       // 4 -> n dimension (64 cols each)
    const int n0 = blockIdx.x * 256;
    const int m0 = blockIdx.y * 128;
    const int which = blockIdx.z;

    const __half* Bw = g_wt[which];

    auto issue_load = [&](int kc, int stage) {
        const size_t koff = (size_t)kc * 64;
        const uint32_t sAh = smem_u32 + stage * STAGE_BYTES;
        const uint32_t sAl = sAh + TILE_A_BYTES;
        const uint32_t sB  = sAh + 2 * TILE_A_BYTES;
        #pragma unroll
        for (int j = 0; j < 2; j++) {
            int ch  = tid + j * 512;         // 0..1023
            int row = ch >> 3;               // 0..127
            int c   = ch & 7;
            uint32_t so = (uint32_t)(row * 128 + ((c ^ (row & 7)) * 16));
            const size_t aoff = (size_t)(m0 + row) * K_ + koff + c * 8;
            CP_ASYNC16(sAh + so, g_xh + aoff);
            CP_ASYNC16(sAl + so, g_xl + aoff);
        }
        #pragma unroll
        for (int j = 0; j < 4; j++) {
            int ch  = tid + j * 512;         // 0..2047
            int row = ch >> 3;               // 0..255
            int c   = ch & 7;
            uint32_t so = (uint32_t)(row * 128 + ((c ^ (row & 7)) * 16));
            CP_ASYNC16(sB + so, Bw + (size_t)(n0 + row) * K_ + koff + c * 8);
        }
        CP_COMMIT();
    };

    const int aRow = warp_m * 32 + (lane & 15);
    const uint32_t aOff0 = (uint32_t)(aRow * 128);
    const uint32_t aOff1 = (uint32_t)((aRow + 16) * 128);
    const int aXor = aRow & 7;
    const int aCsel = lane >> 4;
    const int bRow = warp_n * 64 + ((lane >> 4) << 3) + (lane & 7);   // 0..255
    const int bXor = bRow & 7;
    const int bCsel = (lane >> 3) & 1;
    uint32_t bOff[4];
    #pragma unroll
    for (int g = 0; g < 4; g++) bOff[g] = (uint32_t)((bRow + g * 16) * 128);

    float acc[2][8][4];
    #pragma unroll
    for (int mt = 0; mt < 2; mt++)
        #pragma unroll
        for (int nt = 0; nt < 8; nt++)
            #pragma unroll
            for (int r = 0; r < 4; r++) acc[mt][nt][r] = 0.f;

    issue_load(0, 0);
    issue_load(1, 1);

    for (int kc = 0; kc < 16; kc++) {
        if (kc < 15) CP_WAIT1(); else CP_WAIT0();
        __syncthreads();

        const uint32_t sAh = smem_u32 + (kc & 1) * STAGE_BYTES;
        const uint32_t sAl = sAh + TILE_A_BYTES;
        const uint32_t sB  = sAh + 2 * TILE_A_BYTES;

        #pragma unroll
        for (int ks = 0; ks < 4; ks++) {
            const int ca = ((ks * 2 + aCsel) ^ aXor) * 16;
            const int cb = ((ks * 2 + bCsel) ^ bXor) * 16;

            uint32_t afh[2][4], afl[2][4];
            LDSM_X4(afh[0][0], afh[0][1], afh[0][2], afh[0][3], sAh + aOff0 + ca);
            LDSM_X4(afh[1][0], afh[1][1], afh[1][2], afh[1][3], sAh + aOff1 + ca);
            LDSM_X4(afl[0][0], afl[0][1], afl[0][2], afl[0][3], sAl + aOff0 + ca);
            LDSM_X4(afl[1][0], afl[1][1], afl[1][2], afl[1][3], sAl + aOff1 + ca);

            #pragma unroll
            for (int g = 0; g < 4; g++) {
                uint32_t bf[4];
                LDSM_X4(bf[0], bf[1], bf[2], bf[3], sB + bOff[g] + cb);

                #pragma unroll
                for (int mt = 0; mt < 2; mt++) {
                    MMAF16(acc[mt][g * 2 + 0], afh[mt], bf[0], bf[1]);
                    MMAF16(acc[mt][g * 2 + 1], afh[mt], bf[2], bf[3]);
                    MMAF16(acc[mt][g * 2 + 0], afl[mt], bf[0], bf[1]);
                    MMAF16(acc[mt][g * 2 + 1], afl[mt], bf[2], bf[3]);
                }
            }
        }
        __syncthreads();
        if (kc + 2 < 16) issue_load(kc + 2, kc & 1);
    }

    float* C = (which == 0) ? g_q : (which == 1) ? g_k : g_v;
    const float* bias = (which == 0) ? bq : (which == 1) ? bk : bv;

    #pragma unroll
    for (int mt = 0; mt < 2; mt++) {
        const int r0 = m0 + warp_m * 32 + mt * 16 + (lane >> 2);
        #pragma unroll
        for (int nt = 0; nt < 8; nt++) {
            const int col = n0 + warp_n * 64 + nt * 8 + (lane & 3) * 2;
            const float b0v = __ldg(&bias[col]);
            const float b1v = __ldg(&bias[col + 1]);
            float2 v0 = make_float2(acc[mt][nt][0] + b0v, acc[mt][nt][1] + b1v);
            float2 v1 = make_float2(acc[mt][nt][2] + b0v, acc[mt][nt][3] + b1v);
            *(float2*)&C[(size_t)r0 * N_ + col] = v0;
            *(float2*)&C[(size_t)(r0 + 8) * N_ + col] = v1;
        }
    }
}

// ===========================================================================
// Kernel 3: partial s_ctx over an S-slice + per-column exp-sum.
// Register double-buffer pipeline, LDG.128 loads, LDS.128 V operand,
// packed f32x2 FMA. [unchanged from R13/R14]
// grid (B*NH, SCTX_SPLIT=8), 256 threads, 8 chunks of 32 s-rows per CTA.
// ===========================================================================
__global__ __launch_bounds__(256, 3) void sctx_kernel(const float* __restrict__ mask)
{
    const int bh = blockIdx.x;
    const int part = blockIdx.y;
    const int b = bh >> 4;
    const int h = bh & 15;
    const int tid = threadIdx.x;

    __shared__ float qs[32][64];
    __shared__ float vs[32][64];
    __shared__ float lredf[16][64];

    const int lr = tid >> 4;           // load row base 0..15 (also covers lr+16)
    const int c4 = (tid & 15) * 4;     // fixed 4-column group this thread loads
    const int i4 = (tid / 16) * 4;
    const int j4 = (tid % 16) * 4;

    uint64_t acc2[4][2];
    #pragma unroll
    for (int i = 0; i < 4; i++) { acc2[i][0] = 0ull; acc2[i][1] = 0ull; }
    float4 lsum4 = make_float4(0.f, 0.f, 0.f, 0.f);

    const float* qb = g_q + (size_t)b * S_ * H_ + h * 64;
    const float* vb = g_v + (size_t)b * S_ * H_ + h * 64;
    const float* mb = mask + b * S_;

    constexpr int CHUNKS = (S_ / SCTX_SPLIT) / 32;   // 8
    const int sBeg = part * (S_ / SCTX_SPLIT);

    float4 q0 = *(const float4*)&qb[(size_t)(sBeg + lr) * H_ + c4];
    float4 q1 = *(const float4*)&qb[(size_t)(sBeg + lr + 16) * H_ + c4];
    float4 v0 = *(const float4*)&vb[(size_t)(sBeg + lr) * H_ + c4];
    float4 v1 = *(const float4*)&vb[(size_t)(sBeg + lr + 16) * H_ + c4];
    float m0 = mb[sBeg + lr], m1 = mb[sBeg + lr + 16];

    for (int ch = 0; ch < CHUNKS; ch++) {
        float4 e0, e1;
        e0.x = __expf(q0.x + m0); e0.y = __expf(q0.y + m0);
        e0.z = __expf(q0.z + m0); e0.w = __expf(q0.w + m0);
        e1.x = __expf(q1.x + m1); e1.y = __expf(q1.y + m1);
        e1.z = __expf(q1.z + m1); e1.w = __expf(q1.w + m1);
        lsum4.x += e0.x + e1.x; lsum4.y += e0.y + e1.y;
        lsum4.z += e0.z + e1.z; lsum4.w += e0.w + e1.w;
        *(float4*)&qs[lr][c4]      = e0;
        *(float4*)&qs[lr + 16][c4] = e1;
        *(float4*)&vs[lr][c4]      = v0;
        *(float4*)&vs[lr + 16][c4] = v1;
        __syncthreads();

        if (ch + 1 < CHUNKS) {
            const int s0 = sBeg + (ch + 1) * 32;
            q0 = *(const float4*)&qb[(size_t)(s0 + lr) * H_ + c4];
            q1 = *(const float4*)&qb[(size_t)(s0 + lr + 16) * H_ + c4];
            v0 = *(const float4*)&vb[(size_t)(s0 + lr) * H_ + c4];
            v1 = *(const float4*)&vb[(size_t)(s0 + lr + 16) * H_ + c4];
            m0 = mb[s0 + lr]; m1 = mb[s0 + lr + 16];
        }

        #pragma unroll
        for (int s = 0; s < 32; s++) {
            float ra[4];
            *(float4*)ra = *(const float4*)&qs[s][i4];
            ulonglong2 bv2 = *(const ulonglong2*)&vs[s][j4];
            #pragma unroll
            for (int i = 0; i < 4; i++) {
                uint64_t ad;
                DUP_F32X2(ad, ra[i]);
                FMA_F32X2(acc2[i][0], ad, bv2.x);
                FMA_F32X2(acc2[i][1], ad, bv2.y);
            }
        }
        __syncthreads();
    }

    *(float4*)&lredf[lr][c4] = lsum4;
    __syncthreads();
    if (tid < 64) {
        float s = 0.f;
        #pragma unroll
        for (int g = 0; g < 16; g++) s += lredf[g][tid];
        g_l_part[part][bh][tid] = s;
    }

    float* outp = g_sctx_part[part][bh];
    #pragma unroll
    for (int i = 0; i < 4; i++) {
        float lo0, hi0, lo1, hi1;
        UNPACK_F32X2(lo0, hi0, acc2[i][0]);
        UNPACK_F32X2(lo1, hi1, acc2[i][1]);
        float4 o = make_float4(lo0, hi0, lo1, hi1);
        *(float4*)&outp[(i4 + i) * 64 + j4] = o;
    }
}

// ===========================================================================
// Kernel 3b: reduce Y and l partials + apply 1/l scaling.
// ===========================================================================
__global__ __launch_bounds__(256) void sctx_reduce_kernel()
{
    const int bh = blockIdx.x;
    const int tid = threadIdx.x;

    __shared__ float ilsh[64];
    if (tid < 64) {
        float l = 0.f;
        #pragma unroll
        for (int p = 0; p < SCTX_SPLIT; p++) l += g_l_part[p][bh][tid];
        ilsh[tid] = 1.f / l;
    }
    __syncthreads();

    #pragma unroll
    for (int e = 0; e < 4; e++) {
        int i = (tid + e * 256) * 4;       // float4 element base
        float4 o = make_float4(0.f, 0.f, 0.f, 0.f);
        #pragma unroll
        for (int p = 0; p < SCTX_SPLIT; p++) {
            float4 sp = *(const float4*)&g_sctx_part[p][bh][i];
            o.x += sp.x; o.y += sp.y; o.z += sp.z; o.w += sp.w;
        }
        float il = ilsh[i >> 6];           // row d = i/64
        o.x *= il; o.y *= il; o.z *= il; o.w *= il;
        *(float4*)&g_sctx[(size_t)bh * 4096 + i] = o;
    }
}

// ===========================================================================
// Kernel 4: out = softmax64(K rows) @ s_ctx.
// K loads hoisted before the ss fill; float4 fill; packed f32x2 product.
// [unchanged from R14]
// grid (S/64=32, B*NH=128), 256 threads.
// ===========================================================================
constexpr int OUT_ROWS_PER_WARP = 8;

__global__ __launch_bounds__(256) void out_kernel(float* __restrict__ out)
{
    const int bh = blockIdx.y;
    const int b = bh >> 4;
    const int h = bh & 15;
    const int warp = threadIdx.x >> 5;
    const int lane = threadIdx.x & 31;

    __shared__ float ss[4096];
    __shared__ float cs[8][OUT_ROWS_PER_WARP][64];   // softmax weights per warp/row

    const int sBase = blockIdx.x * (8 * OUT_ROWS_PER_WARP) + warp * OUT_ROWS_PER_WARP;
    const float* kb0 = g_k + ((size_t)b * S_ + sBase) * H_ + h * 64;

    // K loads FIRST (independent of ss) — latency overlaps the fill below
    float kv0[OUT_ROWS_PER_WARP], kv1[OUT_ROWS_PER_WARP];
    #pragma unroll
    for (int i = 0; i < OUT_ROWS_PER_WARP; i++) {
        kv0[i] = kb0[(size_t)i * H_ + lane];
        kv1[i] = kb0[(size_t)i * H_ + lane + 32];
    }

    // ss fill, vectorized (4x LDG.128/STS.128 per thread)
    const float4* sc4 = (const float4*)(g_sctx + (size_t)bh * 4096);
    float4* ss4 = (float4*)ss;
    #pragma unroll
    for (int i = 0; i < 4; i++)
        ss4[threadIdx.x + i * 256] = sc4[threadIdx.x + i * 256];
    __syncthreads();

    // softmax weights (no max subtraction needed: |k| small) -> stage to smem
    #pragma unroll
    for (int i = 0; i < OUT_ROWS_PER_WARP; i++) {
        float e0 = __expf(kv0[i]), e1 = __expf(kv1[i]);
        float sum = e0 + e1;
        #pragma unroll
        for (int off = 16; off; off >>= 1)
            sum += __shfl_xor_sync(0xffffffffu, sum, off);
        float inv = 1.f / sum;
        cs[warp][i][lane]      = e0 * inv;
        cs[warp][i][lane + 32] = e1 * inv;
    }
    __syncwarp();

    uint64_t accp0[OUT_ROWS_PER_WARP], accp1[OUT_ROWS_PER_WARP];
    #pragma unroll
    for (int i = 0; i < OUT_ROWS_PER_WARP; i++) { accp0[i] = 0ull; accp1[i] = 0ull; }

    #pragma unroll
    for (int dc = 0; dc < 4; dc++) {
        float sv0[16], sv1[16];
        #pragma unroll
        for (int d = 0; d < 16; d++) {
            sv0[d] = ss[(dc * 16 + d) * 64 + lane];
            sv1[d] = ss[(dc * 16 + d) * 64 + lane + 32];
        }
        uint64_t sp0[8], sp1[8];
        #pragma unroll
        for (int p = 0; p < 8; p++) {
            PACK_F32X2(sp0[p], sv0[2 * p], sv0[2 * p + 1]);
            PACK_F32X2(sp1[p], sv1[2 * p], sv1[2 * p + 1]);
        }
        #pragma unroll
        for (int i = 0; i < OUT_ROWS_PER_WARP; i++) {
            #pragma unroll
            for (int p = 0; p < 8; p++) {
                uint64_t cpair = *(const uint64_t*)&cs[warp][i][dc * 16 + 2 * p];
                FMA_F32X2(accp0[i], cpair, sp0[p]);
                FMA_F32X2(accp1[i], cpair, sp1[p]);
            }
        }
    }

    #pragma unroll
    for (int i = 0; i < OUT_ROWS_PER_WARP; i++) {
        float l0, h0, l1, h1;
        UNPACK_F32X2(l0, h0, accp0[i]);
        UNPACK_F32X2(l1, h1, accp1[i]);
        float* ob = out + ((size_t)b * S_ + sBase + i) * H_ + h * 64;
        ob[lane]      = l0 + h0;
        ob[lane + 32] = l1 + h1;
    }
}

// ===========================================================================
extern "C" void kernel_launch(void* const* d_in, const int* in_sizes, int n_in,
                              void* d_out, int out_size)
{
    const float* X    = (const float*)d_in[0];
    const float* mask = (const float*)d_in[1];
    const float* Wq   = (const float*)d_in[2];
    const float* bq   = (const float*)d_in[3];
    const float* Wk   = (const float*)d_in[4];
    const float* bk   = (const float*)d_in[5];
    const float* Wv   = (const float*)d_in[6];
    const float* bv   = (const float*)d_in[7];
    float* out = (float*)d_out;

    cudaFuncSetAttribute(qkv_gemm_kernel,
                         cudaFuncAttributeMaxDynamicSharedMemorySize, GEMM_SMEM);

    // prep: fp16 split of X (2-term), single-fp16 W transpose
    split_x_kernel<<<(int)((size_t)M_ * K_ / 4 / 256), 256>>>(X);
    split_w_kernel<<<dim3(N_ / 32, K_ / 32, 3), dim3(32, 8)>>>(Wq, Wk, Wv);

    // HMMA QKV GEMMs (fp16x2: 2 passes, 2048 MMAs/CTA)
    qkv_gemm_kernel<<<dim3(N_ / 256, M_ / 128, 3), 512, GEMM_SMEM>>>(bq, bk, bv);

    // attention tail (pipelined sctx, hoisted-load out, f32x2 FMA)
    sctx_kernel<<<dim3(B_ * NH_, SCTX_SPLIT), 256>>>(mask);
    sctx_reduce_kernel<<<B_ * NH_, 256>>>();
    out_kernel<<<dim3(S_ / 64, B_ * NH_), 256>>>(out);
}